// round 1
// baseline (speedup 1.0000x reference)
#include <cuda_runtime.h>

#define B_      4
#define C_      128
#define N_      4096
#define HEADS_  4
#define DHEAD_  32
#define HID_    128
#define OQKV_   384

// Scratch (static device globals — no runtime allocation)
__device__ float g_mean[B_ * N_];
__device__ float g_rstd[B_ * N_];
__device__ float g_qkv [B_ * OQKV_ * N_];   // [b][o][n], q rows pre-scaled
__device__ float g_attn[B_ * HID_  * N_];   // [b][h*32+d][n]

// ---------------------------------------------------------------------------
// Kernel 1: per-position LayerNorm statistics over C=128 channels
// ---------------------------------------------------------------------------
__global__ void ln_stats_kernel(const float* __restrict__ x) {
    int idx = blockIdx.x * blockDim.x + threadIdx.x;   // b*N + n
    int b = idx >> 12;
    int n = idx & (N_ - 1);
    const float* xp = x + (size_t)b * C_ * N_ + n;
    float s = 0.f, s2 = 0.f;
#pragma unroll 8
    for (int c = 0; c < C_; c++) {
        float v = xp[(size_t)c * N_];
        s += v; s2 += v * v;
    }
    float m   = s  * (1.0f / C_);
    float var = s2 * (1.0f / C_) - m * m;
    g_mean[idx] = m;
    g_rstd[idx] = rsqrtf(var + 1e-5f);
}

// ---------------------------------------------------------------------------
// Tiled GEMM:  Y[b,o,n] = sum_c W[o,c] * Xn[b,c,n]   (+ optional LN / bias / qscale)
// Tile: 64 outputs x 64 positions, K chunked by 32. 256 threads, 4x4 frags.
// ---------------------------------------------------------------------------
template<int ODIM, bool LN, bool QSCALE, bool BIAS>
__global__ __launch_bounds__(256) void gemm_kernel(
    const float* __restrict__ Wm, const float* __restrict__ X,
    float* __restrict__ Y,
    const float* __restrict__ gamma, const float* __restrict__ beta,
    const float* __restrict__ bias)
{
    __shared__ float Ws[32][68];  // [kk][o]
    __shared__ float Xs[32][68];  // [kk][n]

    int b  = blockIdx.z;
    int n0 = blockIdx.x * 64;
    int o0 = blockIdx.y * 64;
    int tid = threadIdx.x;
    int tx = tid & 15, ty = tid >> 4;

    float acc[4][4] = {};
    const float* Xb = X + (size_t)b * C_ * N_;

    for (int k0 = 0; k0 < C_; k0 += 32) {
        { // load W tile, transposed into Ws[kk][ow]
            int ow  = tid >> 2;
            int kk0 = (tid & 3) * 8;
            const float* wp = Wm + (size_t)(o0 + ow) * C_ + k0 + kk0;
#pragma unroll
            for (int t = 0; t < 8; t++) Ws[kk0 + t][ow] = wp[t];
        }
        { // load X tile (LN applied on the fly for the QKV GEMM)
            int kk  = tid >> 3;
            int nx0 = (tid & 7) * 8;
            const float* xp = Xb + (size_t)(k0 + kk) * N_ + n0 + nx0;
            if (LN) {
                float ga = gamma[k0 + kk], be = beta[k0 + kk];
#pragma unroll
                for (int t = 0; t < 8; t++) {
                    int bn = b * N_ + n0 + nx0 + t;
                    Xs[kk][nx0 + t] = (xp[t] - g_mean[bn]) * g_rstd[bn] * ga + be;
                }
            } else {
#pragma unroll
                for (int t = 0; t < 8; t++) Xs[kk][nx0 + t] = xp[t];
            }
        }
        __syncthreads();
#pragma unroll
        for (int kk = 0; kk < 32; kk++) {
            float4 wv = *reinterpret_cast<const float4*>(&Ws[kk][ty * 4]);
            float4 xv = *reinterpret_cast<const float4*>(&Xs[kk][tx * 4]);
            float wa[4] = {wv.x, wv.y, wv.z, wv.w};
            float xa[4] = {xv.x, xv.y, xv.z, xv.w};
#pragma unroll
            for (int r = 0; r < 4; r++)
#pragma unroll
                for (int c = 0; c < 4; c++)
                    acc[r][c] += wa[r] * xa[c];
        }
        __syncthreads();
    }

    const float qscale = 0.17677669529663687f;  // 32^-0.5
#pragma unroll
    for (int r = 0; r < 4; r++) {
        int o = o0 + ty * 4 + r;
        float extra = BIAS ? bias[o] : 0.f;
        float mult  = (QSCALE && o < HID_) ? qscale : 1.f;
        float* yp = Y + ((size_t)b * ODIM + o) * N_ + n0 + tx * 4;
#pragma unroll
        for (int c = 0; c < 4; c++) yp[c] = acc[r][c] * mult + extra;
    }
}

// ---------------------------------------------------------------------------
// Kernel 3: flash attention, one (b,h,i-tile) per block.
// i-tile = 64 rows, j-tile = 64, d = 32. Online softmax.
// ---------------------------------------------------------------------------
__global__ __launch_bounds__(256) void attn_kernel() {
    __shared__ float Qs[32][68];   // [d][i]
    __shared__ float Ks[32][68];   // [d][j]
    __shared__ float Vs[64][33];   // [j][d]
    __shared__ float Ps[64][68];   // [i][j]; reused as [i][d] for output
    __shared__ float m_s[64], l_s[64], a_s[64];

    int bh = blockIdx.y;
    int b = bh >> 2, h = bh & 3;
    int i0 = blockIdx.x * 64;
    int tid = threadIdx.x;
    int tx = tid & 15, ty = tid >> 4;

    const float* qb = g_qkv + ((size_t)(b * OQKV_) +            h * DHEAD_) * N_;
    const float* kb = g_qkv + ((size_t)(b * OQKV_) + HID_     + h * DHEAD_) * N_;
    const float* vb = g_qkv + ((size_t)(b * OQKV_) + 2 * HID_ + h * DHEAD_) * N_;

#pragma unroll
    for (int t = 0; t < 8; t++) {
        int idx = tid + t * 256;
        int d = idx >> 6, i = idx & 63;
        Qs[d][i] = qb[(size_t)d * N_ + i0 + i];
    }
    if (tid < 64) { m_s[tid] = -1e30f; l_s[tid] = 0.f; }
    float o[4][2] = {};
    __syncthreads();

    for (int j0 = 0; j0 < N_; j0 += 64) {
#pragma unroll
        for (int t = 0; t < 8; t++) {
            int idx = tid + t * 256;
            int d = idx >> 6, j = idx & 63;
            Ks[d][j] = kb[(size_t)d * N_ + j0 + j];
            Vs[j][d] = vb[(size_t)d * N_ + j0 + j];
        }
        __syncthreads();

        // S = Q^T K on the 64x64 tile (4x4 per thread)
        float s[4][4] = {};
#pragma unroll
        for (int d = 0; d < 32; d++) {
            float4 qv = *reinterpret_cast<const float4*>(&Qs[d][ty * 4]);
            float4 kv = *reinterpret_cast<const float4*>(&Ks[d][tx * 4]);
            float qa[4] = {qv.x, qv.y, qv.z, qv.w};
            float ka[4] = {kv.x, kv.y, kv.z, kv.w};
#pragma unroll
            for (int r = 0; r < 4; r++)
#pragma unroll
                for (int c = 0; c < 4; c++)
                    s[r][c] += qa[r] * ka[c];
        }

        // online softmax: row reductions across the 16 tx lanes (width-16 xor)
        float m_old[4], m_new[4], rs[4];
#pragma unroll
        for (int r = 0; r < 4; r++) {
            int row = ty * 4 + r;
            m_old[r] = m_s[row];
            float rm = fmaxf(fmaxf(s[r][0], s[r][1]), fmaxf(s[r][2], s[r][3]));
#pragma unroll
            for (int msk = 8; msk >= 1; msk >>= 1)
                rm = fmaxf(rm, __shfl_xor_sync(0xffffffffu, rm, msk, 16));
            m_new[r] = fmaxf(m_old[r], rm);
            float ps = 0.f;
#pragma unroll
            for (int c = 0; c < 4; c++) {
                s[r][c] = __expf(s[r][c] - m_new[r]);
                ps += s[r][c];
            }
#pragma unroll
            for (int msk = 8; msk >= 1; msk >>= 1)
                ps += __shfl_xor_sync(0xffffffffu, ps, msk, 16);
            rs[r] = ps;
        }
        if (tx == 0) {
#pragma unroll
            for (int r = 0; r < 4; r++) {
                int row = ty * 4 + r;
                float alpha = __expf(m_old[r] - m_new[r]);
                m_s[row] = m_new[r];
                l_s[row] = l_s[row] * alpha + rs[r];
                a_s[row] = alpha;
            }
        }
#pragma unroll
        for (int r = 0; r < 4; r++) {
            float4 pv = make_float4(s[r][0], s[r][1], s[r][2], s[r][3]);
            *reinterpret_cast<float4*>(&Ps[ty * 4 + r][tx * 4]) = pv;
        }
        __syncthreads();

        // rescale O, accumulate P @ V^T  (O frag: 4 rows x 2 d per thread)
#pragma unroll
        for (int r = 0; r < 4; r++) {
            float alpha = a_s[ty * 4 + r];
            o[r][0] *= alpha; o[r][1] *= alpha;
        }
#pragma unroll 4
        for (int j = 0; j < 64; j++) {
            float vv0 = Vs[j][tx * 2], vv1 = Vs[j][tx * 2 + 1];
#pragma unroll
            for (int r = 0; r < 4; r++) {
                float p = Ps[ty * 4 + r][j];
                o[r][0] += p * vv0;
                o[r][1] += p * vv1;
            }
        }
        __syncthreads();
    }

    // finalize: divide by l, transpose through smem, coalesced store
#pragma unroll
    for (int r = 0; r < 4; r++) {
        float inv = 1.0f / l_s[ty * 4 + r];
        Ps[ty * 4 + r][tx * 2]     = o[r][0] * inv;
        Ps[ty * 4 + r][tx * 2 + 1] = o[r][1] * inv;
    }
    __syncthreads();
    float* ob = g_attn + ((size_t)b * HID_ + h * DHEAD_) * N_ + i0;
    {
        int i  = tid & 63;
        int d0 = tid >> 6;
#pragma unroll
        for (int t = 0; t < 8; t++) {
            int d = d0 + t * 4;
            ob[(size_t)d * N_ + i] = Ps[i][d];
        }
    }
}

// ---------------------------------------------------------------------------
extern "C" void kernel_launch(void* const* d_in, const int* in_sizes, int n_in,
                              void* d_out, int out_size) {
    const float* x     = (const float*)d_in[0];
    const float* g     = (const float*)d_in[1];
    const float* beta  = (const float*)d_in[2];
    const float* w_qkv = (const float*)d_in[3];
    const float* w_out = (const float*)d_in[4];
    const float* b_out = (const float*)d_in[5];
    float* out = (float*)d_out;

    float* qkv_ptr;  cudaGetSymbolAddress((void**)&qkv_ptr,  g_qkv);
    float* attn_ptr; cudaGetSymbolAddress((void**)&attn_ptr, g_attn);

    ln_stats_kernel<<<(B_ * N_) / 256, 256>>>(x);

    dim3 g2(N_ / 64, OQKV_ / 64, B_);
    gemm_kernel<OQKV_, true, true, false><<<g2, 256>>>(w_qkv, x, qkv_ptr, g, beta, nullptr);

    dim3 g3(N_ / 64, B_ * HEADS_);
    attn_kernel<<<g3, 256>>>();

    dim3 g4(N_ / 64, HID_ / 64, B_);
    gemm_kernel<HID_, false, false, true><<<g4, 256>>>(w_out, attn_ptr, out, nullptr, nullptr, b_out);
}